// round 12
// baseline (speedup 1.0000x reference)
#include <cuda_runtime.h>
#include <cstdint>

#define EPS 1e-06f
#define MAX_V 2000000

#define FP_SCALE   65536.0
#define COUNT_ONE  (1ULL << 48)
#define SUM_MASK   (COUNT_ONE - 1ULL)

#define BLOCK_THREADS   128
#define MIN_BLOCKS_SM   11          // forces regs <= 46 (65536/(128*11))
#define PERSIST_BLOCKS  (148 * MIN_BLOCKS_SM)   // one full resident wave

__device__ float4 g_x4[MAX_V];
__device__ unsigned long long g_packed_acc;
__device__ double g_energy_acc;   // fallback path only

__global__ void __launch_bounds__(256)
repack_kernel(const float* __restrict__ x, int V)
{
    int v = blockIdx.x * blockDim.x + threadIdx.x;
    if (v == 0) {
        g_packed_acc = 0ULL;
        g_energy_acc = 0.0;
    }
    if (v < V) {
        float a = __ldg(x + 3 * v + 0);
        float b = __ldg(x + 3 * v + 1);
        float c = __ldg(x + 3 * v + 2);
        g_x4[v] = make_float4(a, b, c, 0.0f);
    }
}

// Persistent single wave, reg-capped to R10's budget (46) via launch_bounds.
__global__ void __launch_bounds__(BLOCK_THREADS, MIN_BLOCKS_SM)
spring_energy_kernel(const int* __restrict__ indices,  // [E*2] int32
                     const float* __restrict__ l0,
                     const float* __restrict__ k,
                     long long E,
                     float* __restrict__ out)
{
    const long long stride = 4LL * gridDim.x * BLOCK_THREADS;  // edges per sweep
    long long base = 4LL * ((long long)blockIdx.x * BLOCK_THREADS + threadIdx.x);

    float term = 0.0f;

    for (; base + 3 < E; base += stride) {
        const int4*   ip = (const int4*)(indices + 2 * base);
        int4 p = __ldg(ip);
        int4 q = __ldg(ip + 1);
        float4 l04 = __ldg((const float4*)(l0 + base));
        float4 k4  = __ldg((const float4*)(k  + base));

        float4 a0 = __ldg(&g_x4[p.x]);
        float4 b0 = __ldg(&g_x4[p.y]);
        float4 a1 = __ldg(&g_x4[p.z]);
        float4 b1 = __ldg(&g_x4[p.w]);
        float4 a2 = __ldg(&g_x4[q.x]);
        float4 b2 = __ldg(&g_x4[q.y]);
        float4 a3 = __ldg(&g_x4[q.z]);
        float4 b3 = __ldg(&g_x4[q.w]);

        float d0, d1, d2, qq, l, dl;

        d0 = a0.x - b0.x; d1 = a0.y - b0.y; d2 = a0.z - b0.z;
        qq = fmaf(d0, d0, fmaf(d1, d1, d2 * d2));
        l  = sqrtf(qq + EPS); dl = l - l04.x;
        term = fmaf(0.5f * k4.x, dl * dl, term);

        d0 = a1.x - b1.x; d1 = a1.y - b1.y; d2 = a1.z - b1.z;
        qq = fmaf(d0, d0, fmaf(d1, d1, d2 * d2));
        l  = sqrtf(qq + EPS); dl = l - l04.y;
        term = fmaf(0.5f * k4.y, dl * dl, term);

        d0 = a2.x - b2.x; d1 = a2.y - b2.y; d2 = a2.z - b2.z;
        qq = fmaf(d0, d0, fmaf(d1, d1, d2 * d2));
        l  = sqrtf(qq + EPS); dl = l - l04.z;
        term = fmaf(0.5f * k4.z, dl * dl, term);

        d0 = a3.x - b3.x; d1 = a3.y - b3.y; d2 = a3.z - b3.z;
        qq = fmaf(d0, d0, fmaf(d1, d1, d2 * d2));
        l  = sqrtf(qq + EPS); dl = l - l04.w;
        term = fmaf(0.5f * k4.w, dl * dl, term);
    }

    // Remainder (threads whose last chunk straddles E).
    for (long long e = base; e < E; e++) {
        int i = __ldg(indices + 2 * e);
        int j = __ldg(indices + 2 * e + 1);
        float4 a = __ldg(&g_x4[i]);
        float4 b = __ldg(&g_x4[j]);
        float d0 = a.x - b.x, d1 = a.y - b.y, d2 = a.z - b.z;
        float qq = fmaf(d0, d0, fmaf(d1, d1, d2 * d2));
        float l  = sqrtf(qq + EPS);
        float dl = l - __ldg(l0 + e);
        term = fmaf(0.5f * __ldg(k + e), dl * dl, term);
    }

    // Warp reduction
    #pragma unroll
    for (int off = 16; off > 0; off >>= 1)
        term += __shfl_down_sync(0xFFFFFFFFu, term, off);

    // Block reduction (4 warps)
    __shared__ float warp_sums[4];
    int lane = threadIdx.x & 31;
    int wid  = threadIdx.x >> 5;
    if (lane == 0) warp_sums[wid] = term;
    __syncthreads();

    if (wid == 0) {
        float v = (lane < 4) ? warp_sums[lane] : 0.0f;
        #pragma unroll
        for (int off = 2; off > 0; off >>= 1)
            v += __shfl_down_sync(0xFFFFFFFFu, v, off);
        if (lane == 0) {
            unsigned long long add =
                (unsigned long long)((double)v * FP_SCALE + 0.5) + COUNT_ONE;
            unsigned long long old = atomicAdd(&g_packed_acc, add);
            unsigned long long now = old + add;
            if ((now >> 48) == (unsigned long long)gridDim.x) {
                out[0] = (float)((double)(now & SUM_MASK) / FP_SCALE);
            }
        }
    }
}

// ---- Fallback path (V > MAX_V) ----
__global__ void zero_acc_kernel() { g_energy_acc = 0.0; }

__global__ void __launch_bounds__(256)
spring_energy_fallback_kernel(const float* __restrict__ x,
                              const int2* __restrict__ indices,
                              const float* __restrict__ l0,
                              const float* __restrict__ k,
                              long long E)
{
    long long e = (long long)blockIdx.x * blockDim.x + threadIdx.x;
    float term = 0.0f;
    if (e < E) {
        int2 ij = __ldg(indices + e);
        const float* xi = x + 3LL * ij.x;
        const float* xj = x + 3LL * ij.y;
        float d0 = __ldg(xi + 0) - __ldg(xj + 0);
        float d1 = __ldg(xi + 1) - __ldg(xj + 1);
        float d2 = __ldg(xi + 2) - __ldg(xj + 2);
        float q = fmaf(d0, d0, fmaf(d1, d1, d2 * d2));
        float l = sqrtf(q + EPS);
        float dl = l - __ldg(l0 + e);
        term = 0.5f * __ldg(k + e) * dl * dl;
    }
    #pragma unroll
    for (int off = 16; off > 0; off >>= 1)
        term += __shfl_down_sync(0xFFFFFFFFu, term, off);
    __shared__ float warp_sums[8];
    int lane = threadIdx.x & 31;
    int wid  = threadIdx.x >> 5;
    if (lane == 0) warp_sums[wid] = term;
    __syncthreads();
    if (wid == 0) {
        float v = (lane < 8) ? warp_sums[lane] : 0.0f;
        #pragma unroll
        for (int off = 4; off > 0; off >>= 1)
            v += __shfl_down_sync(0xFFFFFFFFu, v, off);
        if (lane == 0)
            atomicAdd(&g_energy_acc, (double)v);
    }
}

__global__ void finalize_kernel(float* out) {
    out[0] = (float)g_energy_acc;
}

extern "C" void kernel_launch(void* const* d_in, const int* in_sizes, int n_in,
                              void* d_out, int out_size)
{
    const float* x       = (const float*)d_in[0];
    const int*   indices = (const int*)d_in[1];
    const float* l0      = (const float*)d_in[2];
    const float* k       = (const float*)d_in[3];
    float*       out     = (float*)d_out;

    int       V = in_sizes[0] / 3;
    long long E = (long long)in_sizes[2];

    if (V <= MAX_V) {
        int vblocks = (V + 255) / 256;
        repack_kernel<<<vblocks, 256>>>(x, V);

        long long chunks = (E + 4LL * BLOCK_THREADS - 1) / (4LL * BLOCK_THREADS);
        int gblocks = (int)(chunks < PERSIST_BLOCKS ? chunks : PERSIST_BLOCKS);
        spring_energy_kernel<<<gblocks, BLOCK_THREADS>>>(indices, l0, k, E, out);
    } else {
        zero_acc_kernel<<<1, 1>>>();
        long long eblocks = (E + 255) / 256;
        spring_energy_fallback_kernel<<<(unsigned)eblocks, 256>>>(
            x, (const int2*)indices, l0, k, E);
        finalize_kernel<<<1, 1>>>(out);
    }
}

// round 13
// speedup vs baseline: 1.1655x; 1.1655x over previous
#include <cuda_runtime.h>
#include <cstdint>

#define EPS 1e-06f
#define MAX_V 2000000

#define FP_SCALE   65536.0
#define COUNT_ONE  (1ULL << 48)
#define SUM_MASK   (COUNT_ONE - 1ULL)

#define TILE_EDGES   1024          // per block
#define BLOCK_THREADS 256          // 4 edges per thread

__device__ float4 g_x4[MAX_V];
__device__ unsigned long long g_packed_acc;
__device__ double g_energy_acc;   // fallback path only

__global__ void __launch_bounds__(256)
repack_kernel(const float* __restrict__ x, int V)
{
    int v = blockIdx.x * blockDim.x + threadIdx.x;
    if (v == 0) {
        g_packed_acc = 0ULL;
        g_energy_acc = 0.0;
    }
    if (v < V) {
        float a = __ldg(x + 3 * v + 0);
        float b = __ldg(x + 3 * v + 1);
        float c = __ldg(x + 3 * v + 2);
        g_x4[v] = make_float4(a, b, c, 0.0f);
    }
}

__device__ __forceinline__ uint32_t smem_u32(const void* p) {
    uint32_t a;
    asm("{ .reg .u64 t; cvta.to.shared.u64 t, %1; cvt.u32.u64 %0, t; }"
        : "=r"(a) : "l"(p));
    return a;
}

// One 1024-edge tile per block. Streaming arrays arrive via cp.async.bulk
// into smem (TMA path, no per-thread L1tex wavefronts); gathers stay on LDG.
__global__ void __launch_bounds__(BLOCK_THREADS)
spring_energy_kernel(const int* __restrict__ indices,  // [E*2] int32
                     const float* __restrict__ l0,
                     const float* __restrict__ k,
                     long long E,
                     float* __restrict__ out)
{
    __shared__ alignas(16) int2  s_idx[TILE_EDGES];   // 8 KB
    __shared__ alignas(16) float s_l0[TILE_EDGES];    // 4 KB
    __shared__ alignas(16) float s_k[TILE_EDGES];     // 4 KB
    __shared__ alignas(8)  unsigned long long s_mbar;

    const int tid = threadIdx.x;
    const long long tile_base = (long long)blockIdx.x * TILE_EDGES;
    const bool full_tile = (tile_base + TILE_EDGES) <= E;

    float term = 0.0f;

    if (full_tile) {
        if (tid == 0) {
            uint32_t mbar = smem_u32(&s_mbar);
            asm volatile("mbarrier.init.shared.b64 [%0], %1;"
                         :: "r"(mbar), "r"(1) : "memory");
            asm volatile("fence.proxy.async.shared::cta;" ::: "memory");
            asm volatile("mbarrier.arrive.expect_tx.shared.b64 _, [%0], %1;"
                         :: "r"(mbar), "r"((uint32_t)(16 * 1024)) : "memory");
            asm volatile(
                "cp.async.bulk.shared::cta.global.mbarrier::complete_tx::bytes"
                " [%0], [%1], %2, [%3];"
                :: "r"(smem_u32(s_idx)),
                   "l"(indices + 2 * tile_base),
                   "r"((uint32_t)(TILE_EDGES * 8)), "r"(mbar) : "memory");
            asm volatile(
                "cp.async.bulk.shared::cta.global.mbarrier::complete_tx::bytes"
                " [%0], [%1], %2, [%3];"
                :: "r"(smem_u32(s_l0)),
                   "l"(l0 + tile_base),
                   "r"((uint32_t)(TILE_EDGES * 4)), "r"(mbar) : "memory");
            asm volatile(
                "cp.async.bulk.shared::cta.global.mbarrier::complete_tx::bytes"
                " [%0], [%1], %2, [%3];"
                :: "r"(smem_u32(s_k)),
                   "l"(k + tile_base),
                   "r"((uint32_t)(TILE_EDGES * 4)), "r"(mbar) : "memory");
        }
        __syncthreads();   // mbarrier init visible to all before waiting

        {
            uint32_t mbar = smem_u32(&s_mbar);
            asm volatile(
                "{\n\t"
                ".reg .pred P;\n\t"
                "W_%=:\n\t"
                "mbarrier.try_wait.parity.acquire.cta.shared::cta.b64 P, [%0], 0, 0x989680;\n\t"
                "@P bra.uni D_%=;\n\t"
                "bra.uni W_%=;\n\t"
                "D_%=:\n\t"
                "}"
                :: "r"(mbar) : "memory");
        }

        // 4 edges per thread from smem; 8 front-batched gathers.
        const int e0 = 4 * tid;
        int2 ij0 = s_idx[e0 + 0];
        int2 ij1 = s_idx[e0 + 1];
        int2 ij2 = s_idx[e0 + 2];
        int2 ij3 = s_idx[e0 + 3];

        float4 a0 = __ldg(&g_x4[ij0.x]);
        float4 b0 = __ldg(&g_x4[ij0.y]);
        float4 a1 = __ldg(&g_x4[ij1.x]);
        float4 b1 = __ldg(&g_x4[ij1.y]);
        float4 a2 = __ldg(&g_x4[ij2.x]);
        float4 b2 = __ldg(&g_x4[ij2.y]);
        float4 a3 = __ldg(&g_x4[ij3.x]);
        float4 b3 = __ldg(&g_x4[ij3.y]);

        float d0, d1, d2, qq, l, dl;

        d0 = a0.x - b0.x; d1 = a0.y - b0.y; d2 = a0.z - b0.z;
        qq = fmaf(d0, d0, fmaf(d1, d1, d2 * d2));
        l  = sqrtf(qq + EPS); dl = l - s_l0[e0 + 0];
        term = fmaf(0.5f * s_k[e0 + 0], dl * dl, term);

        d0 = a1.x - b1.x; d1 = a1.y - b1.y; d2 = a1.z - b1.z;
        qq = fmaf(d0, d0, fmaf(d1, d1, d2 * d2));
        l  = sqrtf(qq + EPS); dl = l - s_l0[e0 + 1];
        term = fmaf(0.5f * s_k[e0 + 1], dl * dl, term);

        d0 = a2.x - b2.x; d1 = a2.y - b2.y; d2 = a2.z - b2.z;
        qq = fmaf(d0, d0, fmaf(d1, d1, d2 * d2));
        l  = sqrtf(qq + EPS); dl = l - s_l0[e0 + 2];
        term = fmaf(0.5f * s_k[e0 + 2], dl * dl, term);

        d0 = a3.x - b3.x; d1 = a3.y - b3.y; d2 = a3.z - b3.z;
        qq = fmaf(d0, d0, fmaf(d1, d1, d2 * d2));
        l  = sqrtf(qq + EPS); dl = l - s_l0[e0 + 3];
        term = fmaf(0.5f * s_k[e0 + 3], dl * dl, term);
    } else {
        // Tail tile: direct loads, per-edge guard.
        for (int u = 0; u < 4; u++) {
            long long e = tile_base + 4LL * tid + u;
            if (e < E) {
                int2 ij = __ldg((const int2*)indices + e);
                float4 a = __ldg(&g_x4[ij.x]);
                float4 b = __ldg(&g_x4[ij.y]);
                float d0 = a.x - b.x, d1 = a.y - b.y, d2 = a.z - b.z;
                float qq = fmaf(d0, d0, fmaf(d1, d1, d2 * d2));
                float l  = sqrtf(qq + EPS);
                float dl = l - __ldg(l0 + e);
                term = fmaf(0.5f * __ldg(k + e), dl * dl, term);
            }
        }
    }

    // Warp reduction
    #pragma unroll
    for (int off = 16; off > 0; off >>= 1)
        term += __shfl_down_sync(0xFFFFFFFFu, term, off);

    // Block reduction (8 warps)
    __shared__ float warp_sums[8];
    int lane = tid & 31;
    int wid  = tid >> 5;
    if (lane == 0) warp_sums[wid] = term;
    __syncthreads();

    if (wid == 0) {
        float v = (lane < 8) ? warp_sums[lane] : 0.0f;
        #pragma unroll
        for (int off = 4; off > 0; off >>= 1)
            v += __shfl_down_sync(0xFFFFFFFFu, v, off);
        if (lane == 0) {
            unsigned long long add =
                (unsigned long long)((double)v * FP_SCALE + 0.5) + COUNT_ONE;
            unsigned long long old = atomicAdd(&g_packed_acc, add);
            unsigned long long now = old + add;
            if ((now >> 48) == (unsigned long long)gridDim.x) {
                out[0] = (float)((double)(now & SUM_MASK) / FP_SCALE);
            }
        }
    }
}

// ---- Fallback path (V > MAX_V) ----
__global__ void zero_acc_kernel() { g_energy_acc = 0.0; }

__global__ void __launch_bounds__(256)
spring_energy_fallback_kernel(const float* __restrict__ x,
                              const int2* __restrict__ indices,
                              const float* __restrict__ l0,
                              const float* __restrict__ k,
                              long long E)
{
    long long e = (long long)blockIdx.x * blockDim.x + threadIdx.x;
    float term = 0.0f;
    if (e < E) {
        int2 ij = __ldg(indices + e);
        const float* xi = x + 3LL * ij.x;
        const float* xj = x + 3LL * ij.y;
        float d0 = __ldg(xi + 0) - __ldg(xj + 0);
        float d1 = __ldg(xi + 1) - __ldg(xj + 1);
        float d2 = __ldg(xi + 2) - __ldg(xj + 2);
        float q = fmaf(d0, d0, fmaf(d1, d1, d2 * d2));
        float l = sqrtf(q + EPS);
        float dl = l - __ldg(l0 + e);
        term = 0.5f * __ldg(k + e) * dl * dl;
    }
    #pragma unroll
    for (int off = 16; off > 0; off >>= 1)
        term += __shfl_down_sync(0xFFFFFFFFu, term, off);
    __shared__ float warp_sums[8];
    int lane = threadIdx.x & 31;
    int wid  = threadIdx.x >> 5;
    if (lane == 0) warp_sums[wid] = term;
    __syncthreads();
    if (wid == 0) {
        float v = (lane < 8) ? warp_sums[lane] : 0.0f;
        #pragma unroll
        for (int off = 4; off > 0; off >>= 1)
            v += __shfl_down_sync(0xFFFFFFFFu, v, off);
        if (lane == 0)
            atomicAdd(&g_energy_acc, (double)v);
    }
}

__global__ void finalize_kernel(float* out) {
    out[0] = (float)g_energy_acc;
}

extern "C" void kernel_launch(void* const* d_in, const int* in_sizes, int n_in,
                              void* d_out, int out_size)
{
    const float* x       = (const float*)d_in[0];
    const int*   indices = (const int*)d_in[1];
    const float* l0      = (const float*)d_in[2];
    const float* k       = (const float*)d_in[3];
    float*       out     = (float*)d_out;

    int       V = in_sizes[0] / 3;
    long long E = (long long)in_sizes[2];

    if (V <= MAX_V) {
        int vblocks = (V + 255) / 256;
        repack_kernel<<<vblocks, 256>>>(x, V);

        long long gblocks = (E + TILE_EDGES - 1) / TILE_EDGES;
        spring_energy_kernel<<<(unsigned)gblocks, BLOCK_THREADS>>>(
            indices, l0, k, E, out);
    } else {
        zero_acc_kernel<<<1, 1>>>();
        long long eblocks = (E + 255) / 256;
        spring_energy_fallback_kernel<<<(unsigned)eblocks, 256>>>(
            x, (const int2*)indices, l0, k, E);
        finalize_kernel<<<1, 1>>>(out);
    }
}

// round 14
// speedup vs baseline: 1.2575x; 1.0789x over previous
#include <cuda_runtime.h>
#include <cstdint>

#define EPS 1e-06f
#define MAX_V 2000000

#define FP_SCALE   65536.0
#define COUNT_ONE  (1ULL << 48)
#define SUM_MASK   (COUNT_ONE - 1ULL)

__device__ float4 g_x4[MAX_V];
__device__ unsigned long long g_packed_acc;
__device__ double g_energy_acc;   // fallback path only

// Repack x[V,3] -> g_x4[V]; triggers dependent launch once this block's
// stores are done.
__global__ void __launch_bounds__(256)
repack_kernel(const float* __restrict__ x, int V)
{
    int v = blockIdx.x * blockDim.x + threadIdx.x;
    if (v == 0) {
        g_packed_acc = 0ULL;
        g_energy_acc = 0.0;
    }
    if (v < V) {
        float a = __ldg(x + 3 * v + 0);
        float b = __ldg(x + 3 * v + 1);
        float c = __ldg(x + 3 * v + 2);
        g_x4[v] = make_float4(a, b, c, 0.0f);
    }
    __syncthreads();
#if __CUDA_ARCH__ >= 900
    cudaTriggerProgrammaticLaunchCompletion();
#endif
}

// R7-best shape: 4 edges/thread, 256-thread blocks, flat grid.
// PDL: streaming loads issue BEFORE the grid-dependency sync; gathers after.
__global__ void __launch_bounds__(256)
spring_energy_kernel(const int* __restrict__ indices,  // [E*2] int32
                     const float* __restrict__ l0,
                     const float* __restrict__ k,
                     long long E,
                     float* __restrict__ out)
{
    long long t    = (long long)blockIdx.x * blockDim.x + threadIdx.x;
    long long base = 4 * t;

    float term = 0.0f;
    if (base + 3 < E) {
        // Streaming loads — independent of g_x4, overlap with repack tail.
        int4 p = __ldg((const int4*)(indices + 2 * base));
        int4 q = __ldg((const int4*)(indices + 2 * base) + 1);
        float4 l04 = __ldg((const float4*)(l0 + base));
        float4 k4  = __ldg((const float4*)(k  + base));

#if __CUDA_ARCH__ >= 900
        cudaGridDependencySynchronize();
#endif

        float4 a0 = __ldg(&g_x4[p.x]);
        float4 b0 = __ldg(&g_x4[p.y]);
        float4 a1 = __ldg(&g_x4[p.z]);
        float4 b1 = __ldg(&g_x4[p.w]);
        float4 a2 = __ldg(&g_x4[q.x]);
        float4 b2 = __ldg(&g_x4[q.y]);
        float4 a3 = __ldg(&g_x4[q.z]);
        float4 b3 = __ldg(&g_x4[q.w]);

        float d0, d1, d2, qq, l, dl;

        d0 = a0.x - b0.x; d1 = a0.y - b0.y; d2 = a0.z - b0.z;
        qq = fmaf(d0, d0, fmaf(d1, d1, d2 * d2));
        l  = sqrtf(qq + EPS); dl = l - l04.x;
        term = fmaf(k4.x, dl * dl, term);

        d0 = a1.x - b1.x; d1 = a1.y - b1.y; d2 = a1.z - b1.z;
        qq = fmaf(d0, d0, fmaf(d1, d1, d2 * d2));
        l  = sqrtf(qq + EPS); dl = l - l04.y;
        term = fmaf(k4.y, dl * dl, term);

        d0 = a2.x - b2.x; d1 = a2.y - b2.y; d2 = a2.z - b2.z;
        qq = fmaf(d0, d0, fmaf(d1, d1, d2 * d2));
        l  = sqrtf(qq + EPS); dl = l - l04.z;
        term = fmaf(k4.z, dl * dl, term);

        d0 = a3.x - b3.x; d1 = a3.y - b3.y; d2 = a3.z - b3.z;
        qq = fmaf(d0, d0, fmaf(d1, d1, d2 * d2));
        l  = sqrtf(qq + EPS); dl = l - l04.w;
        term = fmaf(k4.w, dl * dl, term);
    } else {
#if __CUDA_ARCH__ >= 900
        cudaGridDependencySynchronize();
#endif
        for (long long e = base; e < E; e++) {
            int i = __ldg(indices + 2 * e);
            int j = __ldg(indices + 2 * e + 1);
            float4 a = __ldg(&g_x4[i]);
            float4 b = __ldg(&g_x4[j]);
            float d0 = a.x - b.x, d1 = a.y - b.y, d2 = a.z - b.z;
            float qq = fmaf(d0, d0, fmaf(d1, d1, d2 * d2));
            float l  = sqrtf(qq + EPS);
            float dl = l - __ldg(l0 + e);
            term = fmaf(__ldg(k + e), dl * dl, term);
        }
    }

    // Warp reduction
    #pragma unroll
    for (int off = 16; off > 0; off >>= 1)
        term += __shfl_down_sync(0xFFFFFFFFu, term, off);

    // Block reduction
    __shared__ float warp_sums[8];
    int lane = threadIdx.x & 31;
    int wid  = threadIdx.x >> 5;
    if (lane == 0) warp_sums[wid] = term;
    __syncthreads();

    if (wid == 0) {
        float v = (lane < 8) ? warp_sums[lane] : 0.0f;
        #pragma unroll
        for (int off = 4; off > 0; off >>= 1)
            v += __shfl_down_sync(0xFFFFFFFFu, v, off);
        if (lane == 0) {
            unsigned long long add =
                (unsigned long long)((double)v * FP_SCALE + 0.5) + COUNT_ONE;
            unsigned long long old = atomicAdd(&g_packed_acc, add);
            unsigned long long now = old + add;
            if ((now >> 48) == (unsigned long long)gridDim.x) {
                // 0.5 factor applied once here.
                out[0] = (float)(0.5 * (double)(now & SUM_MASK) / FP_SCALE);
            }
        }
    }
}

// ---- Fallback path (V > MAX_V) ----
__global__ void zero_acc_kernel() { g_energy_acc = 0.0; }

__global__ void __launch_bounds__(256)
spring_energy_fallback_kernel(const float* __restrict__ x,
                              const int2* __restrict__ indices,
                              const float* __restrict__ l0,
                              const float* __restrict__ k,
                              long long E)
{
    long long e = (long long)blockIdx.x * blockDim.x + threadIdx.x;
    float term = 0.0f;
    if (e < E) {
        int2 ij = __ldg(indices + e);
        const float* xi = x + 3LL * ij.x;
        const float* xj = x + 3LL * ij.y;
        float d0 = __ldg(xi + 0) - __ldg(xj + 0);
        float d1 = __ldg(xi + 1) - __ldg(xj + 1);
        float d2 = __ldg(xi + 2) - __ldg(xj + 2);
        float q = fmaf(d0, d0, fmaf(d1, d1, d2 * d2));
        float l = sqrtf(q + EPS);
        float dl = l - __ldg(l0 + e);
        term = 0.5f * __ldg(k + e) * dl * dl;
    }
    #pragma unroll
    for (int off = 16; off > 0; off >>= 1)
        term += __shfl_down_sync(0xFFFFFFFFu, term, off);
    __shared__ float warp_sums[8];
    int lane = threadIdx.x & 31;
    int wid  = threadIdx.x >> 5;
    if (lane == 0) warp_sums[wid] = term;
    __syncthreads();
    if (wid == 0) {
        float v = (lane < 8) ? warp_sums[lane] : 0.0f;
        #pragma unroll
        for (int off = 4; off > 0; off >>= 1)
            v += __shfl_down_sync(0xFFFFFFFFu, v, off);
        if (lane == 0)
            atomicAdd(&g_energy_acc, (double)v);
    }
}

__global__ void finalize_kernel(float* out) {
    out[0] = (float)g_energy_acc;
}

extern "C" void kernel_launch(void* const* d_in, const int* in_sizes, int n_in,
                              void* d_out, int out_size)
{
    const float* x       = (const float*)d_in[0];
    const int*   indices = (const int*)d_in[1];
    const float* l0      = (const float*)d_in[2];
    const float* k       = (const float*)d_in[3];
    float*       out     = (float*)d_out;

    int       V = in_sizes[0] / 3;
    long long E = (long long)in_sizes[2];

    if (V <= MAX_V) {
        int vblocks = (V + 255) / 256;
        repack_kernel<<<vblocks, 256>>>(x, V);

        const int threads = 256;
        long long eblocks = (E + 4LL * threads - 1) / (4LL * threads);

        // PDL launch: energy kernel may begin while repack drains; the
        // in-kernel grid-dependency sync enforces correctness.
        cudaLaunchConfig_t cfg = {};
        cfg.gridDim  = dim3((unsigned)eblocks, 1, 1);
        cfg.blockDim = dim3(threads, 1, 1);
        cfg.dynamicSmemBytes = 0;
        cfg.stream = 0;
        cudaLaunchAttribute attrs[1];
        attrs[0].id = cudaLaunchAttributeProgrammaticStreamSerialization;
        attrs[0].val.programmaticStreamSerializationAllowed = 1;
        cfg.attrs = attrs;
        cfg.numAttrs = 1;

        cudaError_t err = cudaLaunchKernelEx(&cfg, spring_energy_kernel,
                                             indices, l0, k, E, out);
        if (err != cudaSuccess) {
            // Fall back to a plain launch (sync still correct: dependency
            // satisfied because repack completed before us in-stream).
            spring_energy_kernel<<<(unsigned)eblocks, threads>>>(
                indices, l0, k, E, out);
        }
    } else {
        zero_acc_kernel<<<1, 1>>>();
        long long eblocks = (E + 255) / 256;
        spring_energy_fallback_kernel<<<(unsigned)eblocks, 256>>>(
            x, (const int2*)indices, l0, k, E);
        finalize_kernel<<<1, 1>>>(out);
    }
}

// round 15
// speedup vs baseline: 1.3639x; 1.0847x over previous
#include <cuda_runtime.h>
#include <cuda_fp16.h>
#include <cstdint>

#define EPS 1e-06f
#define MAX_V 2000000

#define FP_SCALE   65536.0
#define COUNT_ONE  (1ULL << 48)
#define SUM_MASK   (COUNT_ONE - 1ULL)

// Packed half-precision vertex table: .x = half2(x,y), .y = half2(z,0).
__device__ uint2 g_xh[MAX_V];
__device__ unsigned long long g_packed_acc;
__device__ double g_energy_acc;   // fallback path only

__global__ void __launch_bounds__(256)
repack_kernel(const float* __restrict__ x, int V)
{
    int v = blockIdx.x * blockDim.x + threadIdx.x;
    if (v == 0) {
        g_packed_acc = 0ULL;
        g_energy_acc = 0.0;
    }
    if (v < V) {
        float a = __ldg(x + 3 * v + 0);
        float b = __ldg(x + 3 * v + 1);
        float c = __ldg(x + 3 * v + 2);
        half2 xy = __floats2half2_rn(a, b);
        half2 z0 = __floats2half2_rn(c, 0.0f);
        uint2 packed;
        packed.x = *(const unsigned int*)&xy;
        packed.y = *(const unsigned int*)&z0;
        g_xh[v] = packed;
    }
}

__device__ __forceinline__ float3 unpack_v(uint2 p)
{
    half2 xy = *(const half2*)&p.x;
    half2 z0 = *(const half2*)&p.y;
    float2 fxy = __half22float2(xy);
    return make_float3(fxy.x, fxy.y, __low2float(z0));
}

// 4 edges per thread, 256-thread blocks (best measured shape).
// 8 front-batched 8B gathers; fp32 math; one packed atomic per block.
__global__ void __launch_bounds__(256)
spring_energy_kernel(const int* __restrict__ indices,  // [E*2] int32
                     const float* __restrict__ l0,
                     const float* __restrict__ k,
                     long long E,
                     float* __restrict__ out)
{
    long long t    = (long long)blockIdx.x * blockDim.x + threadIdx.x;
    long long base = 4 * t;

    float term = 0.0f;
    if (base + 3 < E) {
        int4 p = __ldg((const int4*)(indices + 2 * base));
        int4 q = __ldg((const int4*)(indices + 2 * base) + 1);
        float4 l04 = __ldg((const float4*)(l0 + base));
        float4 k4  = __ldg((const float4*)(k  + base));

        uint2 ra0 = __ldg(&g_xh[p.x]);
        uint2 rb0 = __ldg(&g_xh[p.y]);
        uint2 ra1 = __ldg(&g_xh[p.z]);
        uint2 rb1 = __ldg(&g_xh[p.w]);
        uint2 ra2 = __ldg(&g_xh[q.x]);
        uint2 rb2 = __ldg(&g_xh[q.y]);
        uint2 ra3 = __ldg(&g_xh[q.z]);
        uint2 rb3 = __ldg(&g_xh[q.w]);

        float3 a, b;
        float d0, d1, d2, qq, l, dl;

        a = unpack_v(ra0); b = unpack_v(rb0);
        d0 = a.x - b.x; d1 = a.y - b.y; d2 = a.z - b.z;
        qq = fmaf(d0, d0, fmaf(d1, d1, d2 * d2));
        l  = sqrtf(qq + EPS); dl = l - l04.x;
        term = fmaf(k4.x, dl * dl, term);

        a = unpack_v(ra1); b = unpack_v(rb1);
        d0 = a.x - b.x; d1 = a.y - b.y; d2 = a.z - b.z;
        qq = fmaf(d0, d0, fmaf(d1, d1, d2 * d2));
        l  = sqrtf(qq + EPS); dl = l - l04.y;
        term = fmaf(k4.y, dl * dl, term);

        a = unpack_v(ra2); b = unpack_v(rb2);
        d0 = a.x - b.x; d1 = a.y - b.y; d2 = a.z - b.z;
        qq = fmaf(d0, d0, fmaf(d1, d1, d2 * d2));
        l  = sqrtf(qq + EPS); dl = l - l04.z;
        term = fmaf(k4.z, dl * dl, term);

        a = unpack_v(ra3); b = unpack_v(rb3);
        d0 = a.x - b.x; d1 = a.y - b.y; d2 = a.z - b.z;
        qq = fmaf(d0, d0, fmaf(d1, d1, d2 * d2));
        l  = sqrtf(qq + EPS); dl = l - l04.w;
        term = fmaf(k4.w, dl * dl, term);
    } else {
        for (long long e = base; e < E; e++) {
            int i = __ldg(indices + 2 * e);
            int j = __ldg(indices + 2 * e + 1);
            float3 a = unpack_v(__ldg(&g_xh[i]));
            float3 b = unpack_v(__ldg(&g_xh[j]));
            float d0 = a.x - b.x, d1 = a.y - b.y, d2 = a.z - b.z;
            float qq = fmaf(d0, d0, fmaf(d1, d1, d2 * d2));
            float l  = sqrtf(qq + EPS);
            float dl = l - __ldg(l0 + e);
            term = fmaf(__ldg(k + e), dl * dl, term);
        }
    }

    // Warp reduction
    #pragma unroll
    for (int off = 16; off > 0; off >>= 1)
        term += __shfl_down_sync(0xFFFFFFFFu, term, off);

    // Block reduction
    __shared__ float warp_sums[8];
    int lane = threadIdx.x & 31;
    int wid  = threadIdx.x >> 5;
    if (lane == 0) warp_sums[wid] = term;
    __syncthreads();

    if (wid == 0) {
        float v = (lane < 8) ? warp_sums[lane] : 0.0f;
        #pragma unroll
        for (int off = 4; off > 0; off >>= 1)
            v += __shfl_down_sync(0xFFFFFFFFu, v, off);
        if (lane == 0) {
            unsigned long long add =
                (unsigned long long)((double)v * FP_SCALE + 0.5) + COUNT_ONE;
            unsigned long long old = atomicAdd(&g_packed_acc, add);
            unsigned long long now = old + add;
            if ((now >> 48) == (unsigned long long)gridDim.x) {
                out[0] = (float)(0.5 * (double)(now & SUM_MASK) / FP_SCALE);
            }
        }
    }
}

// ---- Fallback path (V > MAX_V): full fp32, direct gather from x ----
__global__ void zero_acc_kernel() { g_energy_acc = 0.0; }

__global__ void __launch_bounds__(256)
spring_energy_fallback_kernel(const float* __restrict__ x,
                              const int2* __restrict__ indices,
                              const float* __restrict__ l0,
                              const float* __restrict__ k,
                              long long E)
{
    long long e = (long long)blockIdx.x * blockDim.x + threadIdx.x;
    float term = 0.0f;
    if (e < E) {
        int2 ij = __ldg(indices + e);
        const float* xi = x + 3LL * ij.x;
        const float* xj = x + 3LL * ij.y;
        float d0 = __ldg(xi + 0) - __ldg(xj + 0);
        float d1 = __ldg(xi + 1) - __ldg(xj + 1);
        float d2 = __ldg(xi + 2) - __ldg(xj + 2);
        float q = fmaf(d0, d0, fmaf(d1, d1, d2 * d2));
        float l = sqrtf(q + EPS);
        float dl = l - __ldg(l0 + e);
        term = 0.5f * __ldg(k + e) * dl * dl;
    }
    #pragma unroll
    for (int off = 16; off > 0; off >>= 1)
        term += __shfl_down_sync(0xFFFFFFFFu, term, off);
    __shared__ float warp_sums[8];
    int lane = threadIdx.x & 31;
    int wid  = threadIdx.x >> 5;
    if (lane == 0) warp_sums[wid] = term;
    __syncthreads();
    if (wid == 0) {
        float v = (lane < 8) ? warp_sums[lane] : 0.0f;
        #pragma unroll
        for (int off = 4; off > 0; off >>= 1)
            v += __shfl_down_sync(0xFFFFFFFFu, v, off);
        if (lane == 0)
            atomicAdd(&g_energy_acc, (double)v);
    }
}

__global__ void finalize_kernel(float* out) {
    out[0] = (float)g_energy_acc;
}

extern "C" void kernel_launch(void* const* d_in, const int* in_sizes, int n_in,
                              void* d_out, int out_size)
{
    const float* x       = (const float*)d_in[0];
    const int*   indices = (const int*)d_in[1];
    const float* l0      = (const float*)d_in[2];
    const float* k       = (const float*)d_in[3];
    float*       out     = (float*)d_out;

    int       V = in_sizes[0] / 3;
    long long E = (long long)in_sizes[2];

    if (V <= MAX_V) {
        int vblocks = (V + 255) / 256;
        repack_kernel<<<vblocks, 256>>>(x, V);

        const int threads = 256;
        long long eblocks = (E + 4LL * threads - 1) / (4LL * threads);
        spring_energy_kernel<<<(unsigned)eblocks, threads>>>(indices, l0, k, E, out);
    } else {
        zero_acc_kernel<<<1, 1>>>();
        long long eblocks = (E + 255) / 256;
        spring_energy_fallback_kernel<<<(unsigned)eblocks, 256>>>(
            x, (const int2*)indices, l0, k, E);
        finalize_kernel<<<1, 1>>>(out);
    }
}